// round 9
// baseline (speedup 1.0000x reference)
#include <cuda_runtime.h>
#include <cstdint>

#define N_NODES 100000
#define N_EDGES 50000
#define C 128
#define C4 (C / 4)
#define NNZ 1600000
#define FULL 0xFFFFFFFFu

// ---------------------------------------------------------------------------
// Scratch (allocation-free __device__ globals)
__device__ int   g_deg_v[N_NODES];
__device__ int   g_deg_e[N_EDGES];
__device__ float g_inv_v[N_NODES];
__device__ float g_inv_e[N_EDGES];
__device__ int   g_off_e[N_EDGES + 1];
__device__ int   g_off_v[N_NODES + 1];
__device__ int   g_cur_e[N_EDGES];
__device__ int   g_cur_v[N_NODES];
__device__ int   g_csr_e_nodes[NNZ];   // per-edge list of incident nodes
__device__ int   g_csr_v_edges[NNZ];   // per-node list of incident edges
__device__ __align__(16) float g_sw0[C];
__device__ __align__(16) float g_sw1[C];

// ---------------------------------------------------------------------------
__global__ void k_zero_deg() {
    int i = blockIdx.x * blockDim.x + threadIdx.x;
    if (i < N_NODES) g_deg_v[i] = 0;
    if (i < N_EDGES) g_deg_e[i] = 0;
}

__global__ void k_softmax(const float* __restrict__ lw) {
    int c = threadIdx.x;  // C threads
    float w0 = lw[c], w1 = lw[C + c];
    float m = fmaxf(w0, w1);
    float e0 = expf(w0 - m), e1 = expf(w1 - m);
    float inv = 1.0f / (e0 + e1);
    g_sw0[c] = e0 * inv;
    g_sw1[c] = e1 * inv;
}

__global__ void k_degrees(const int* __restrict__ nidx,
                          const int* __restrict__ eidx) {
    int i = blockIdx.x * blockDim.x + threadIdx.x;
    if (i < NNZ) {
        atomicAdd(&g_deg_v[__ldg(&nidx[i])], 1);
        atomicAdd(&g_deg_e[__ldg(&eidx[i])], 1);
    }
}

// Single-block exclusive scan of deg[0..n) -> off/cur, plus inv-degree.
__global__ void k_scan(const int* __restrict__ deg, int n,
                       int* __restrict__ off, int* __restrict__ cur,
                       float* __restrict__ inv) {
    __shared__ int sh[1024];
    int tid = threadIdx.x;
    int chunk = (n + 1023) >> 10;
    int beg = tid * chunk;
    int end = min(beg + chunk, n);
    int sum = 0;
    for (int i = beg; i < end; i++) sum += deg[i];
    sh[tid] = sum;
    __syncthreads();
    // Hillis-Steele inclusive scan over 1024 partials
    for (int d = 1; d < 1024; d <<= 1) {
        int v = (tid >= d) ? sh[tid - d] : 0;
        __syncthreads();
        sh[tid] += v;
        __syncthreads();
    }
    int run = (tid == 0) ? 0 : sh[tid - 1];
    for (int i = beg; i < end; i++) {
        off[i] = run;
        cur[i] = run;
        int d = deg[i];
        inv[i] = (d > 0) ? (1.0f / (float)d) : 0.0f;
        run += d;
    }
    if (tid == 0) off[n] = NNZ;
}

// Build both CSR adjacency lists in one pass.
__global__ void k_permute(const int* __restrict__ nidx,
                          const int* __restrict__ eidx) {
    int i = blockIdx.x * blockDim.x + threadIdx.x;
    if (i >= NNZ) return;
    int nd = __ldg(&nidx[i]);
    int ed = __ldg(&eidx[i]);
    int pe = atomicAdd(&g_cur_e[ed], 1);
    g_csr_e_nodes[pe] = nd;
    int pv = atomicAdd(&g_cur_v[nd], 1);
    g_csr_v_edges[pv] = ed;
}

// ---------------------------------------------------------------------------
// v2e gather: one warp per edge.
// edge_out[e] = sw0 * sum_{n in e}(X[n] * inv_v[n]) + sw1 * Y[e]
__global__ void k_v2e_gather(const float4* __restrict__ X4,
                             const float4* __restrict__ Y4,
                             float4* __restrict__ edge_out4) {
    int e = (blockIdx.x * blockDim.x + threadIdx.x) >> 5;
    int lane = threadIdx.x & 31;
    if (e >= N_EDGES) return;
    int beg = __ldg(&g_off_e[e]);
    int end = __ldg(&g_off_e[e + 1]);
    float4 acc = make_float4(0.f, 0.f, 0.f, 0.f);
    for (int base = beg; base < end; base += 32) {
        int cnt = min(32, end - base);
        int my = (lane < cnt) ? __ldg(&g_csr_e_nodes[base + lane]) : 0;
        for (int t = 0; t < cnt; t++) {
            int node = __shfl_sync(FULL, my, t);
            float s = __ldg(&g_inv_v[node]);
            float4 v = __ldg(&X4[(size_t)node * C4 + lane]);
            acc.x += s * v.x; acc.y += s * v.y;
            acc.z += s * v.z; acc.w += s * v.w;
        }
    }
    float4 s0 = reinterpret_cast<const float4*>(g_sw0)[lane];
    float4 s1 = reinterpret_cast<const float4*>(g_sw1)[lane];
    float4 y = __ldg(&Y4[(size_t)e * C4 + lane]);
    float4 o;
    o.x = s0.x * acc.x + s1.x * y.x;
    o.y = s0.y * acc.y + s1.y * y.y;
    o.z = s0.z * acc.z + s1.z * y.z;
    o.w = s0.w * acc.w + s1.w * y.w;
    edge_out4[(size_t)e * C4 + lane] = o;
}

// e2v gather: one warp per node.
// node_out[n] = sw0 * sum_{e ni n}(edge_feat[e] * inv_e[e]) + sw1 * X[n]
__global__ void k_e2v_gather(const float4* __restrict__ edge_feat4,
                             const float4* __restrict__ X4,
                             float4* __restrict__ node_out4) {
    int n = (blockIdx.x * blockDim.x + threadIdx.x) >> 5;
    int lane = threadIdx.x & 31;
    if (n >= N_NODES) return;
    int beg = __ldg(&g_off_v[n]);
    int end = __ldg(&g_off_v[n + 1]);
    float4 acc = make_float4(0.f, 0.f, 0.f, 0.f);
    for (int base = beg; base < end; base += 32) {
        int cnt = min(32, end - base);
        int my = (lane < cnt) ? __ldg(&g_csr_v_edges[base + lane]) : 0;
        for (int t = 0; t < cnt; t++) {
            int edge = __shfl_sync(FULL, my, t);
            float s = __ldg(&g_inv_e[edge]);
            float4 v = __ldg(&edge_feat4[(size_t)edge * C4 + lane]);
            acc.x += s * v.x; acc.y += s * v.y;
            acc.z += s * v.z; acc.w += s * v.w;
        }
    }
    float4 s0 = reinterpret_cast<const float4*>(g_sw0)[lane];
    float4 s1 = reinterpret_cast<const float4*>(g_sw1)[lane];
    float4 x = __ldg(&X4[(size_t)n * C4 + lane]);
    float4 o;
    o.x = s0.x * acc.x + s1.x * x.x;
    o.y = s0.y * acc.y + s1.y * x.y;
    o.z = s0.z * acc.z + s1.z * x.z;
    o.w = s0.w * acc.w + s1.w * x.w;
    node_out4[(size_t)n * C4 + lane] = o;
}

// ---------------------------------------------------------------------------
extern "C" void kernel_launch(void* const* d_in, const int* in_sizes, int n_in,
                              void* d_out, int out_size) {
    const float* X    = (const float*)d_in[0];  // [N, C]
    const float* Y    = (const float*)d_in[1];  // [E, C]
    const float* lw   = (const float*)d_in[2];  // [2, C]
    const int*   nidx = (const int*)d_in[3];    // [NNZ]  (JAX demotes int64->int32)
    const int*   eidx = (const int*)d_in[4];    // [NNZ]

    float* node_out = (float*)d_out;                   // [N, C]
    float* edge_out = node_out + (size_t)N_NODES * C;  // [E, C]

    // Pointers to __device__ globals usable as kernel args
    int *p_deg_e, *p_deg_v, *p_off_e, *p_off_v, *p_cur_e, *p_cur_v;
    float *p_inv_e, *p_inv_v;
    cudaGetSymbolAddress((void**)&p_deg_e, g_deg_e);
    cudaGetSymbolAddress((void**)&p_deg_v, g_deg_v);
    cudaGetSymbolAddress((void**)&p_off_e, g_off_e);
    cudaGetSymbolAddress((void**)&p_off_v, g_off_v);
    cudaGetSymbolAddress((void**)&p_cur_e, g_cur_e);
    cudaGetSymbolAddress((void**)&p_cur_v, g_cur_v);
    cudaGetSymbolAddress((void**)&p_inv_e, g_inv_e);
    cudaGetSymbolAddress((void**)&p_inv_v, g_inv_v);

    k_zero_deg<<<(N_NODES + 255) / 256, 256>>>();
    k_softmax<<<1, C>>>(lw);
    k_degrees<<<(NNZ + 255) / 256, 256>>>(nidx, eidx);
    k_scan<<<1, 1024>>>(p_deg_e, N_EDGES, p_off_e, p_cur_e, p_inv_e);
    k_scan<<<1, 1024>>>(p_deg_v, N_NODES, p_off_v, p_cur_v, p_inv_v);
    k_permute<<<(NNZ + 255) / 256, 256>>>(nidx, eidx);

    // Gather passes (warp per row), softmax mix fused in epilogue
    k_v2e_gather<<<(N_EDGES * 32 + 255) / 256, 256>>>(
        (const float4*)X, (const float4*)Y, (float4*)edge_out);
    k_e2v_gather<<<(N_NODES * 32 + 255) / 256, 256>>>(
        (const float4*)edge_out, (const float4*)X, (float4*)node_out);
}

// round 12
// speedup vs baseline: 2.3510x; 2.3510x over previous
#include <cuda_runtime.h>
#include <cstdint>

#define N_NODES 100000
#define N_EDGES 50000
#define C 128
#define C4 (C / 4)
#define NNZ 1600000
#define FULL 0xFFFFFFFFu
#define TILE 1024   // elements per scan block (256 thr x 4)

// ---------------------------------------------------------------------------
// Scratch (allocation-free __device__ globals)
__device__ int   g_deg_v[N_NODES];
__device__ int   g_deg_e[N_EDGES];
__device__ float g_inv_v[N_NODES];
__device__ float g_inv_e[N_EDGES];
__device__ int   g_off_e[N_EDGES + 1];
__device__ int   g_off_v[N_NODES + 1];
__device__ int   g_cur_e[N_EDGES];
__device__ int   g_cur_v[N_NODES];
__device__ int   g_bsum_e[128];
__device__ int   g_bsum_v[128];
__device__ int   g_csr_e_nodes[NNZ];   // per-edge list of incident nodes
__device__ int   g_csr_v_edges[NNZ];   // per-node list of incident edges
__device__ __align__(16) float g_sw0[C];
__device__ __align__(16) float g_sw1[C];

// ---------------------------------------------------------------------------
__global__ void k_zero_deg() {
    int i = blockIdx.x * blockDim.x + threadIdx.x;
    if (i < N_NODES) g_deg_v[i] = 0;
    if (i < N_EDGES) g_deg_e[i] = 0;
}

__global__ void k_softmax(const float* __restrict__ lw) {
    int c = threadIdx.x;  // C threads
    float w0 = lw[c], w1 = lw[C + c];
    float m = fmaxf(w0, w1);
    float e0 = expf(w0 - m), e1 = expf(w1 - m);
    float inv = 1.0f / (e0 + e1);
    g_sw0[c] = e0 * inv;
    g_sw1[c] = e1 * inv;
}

__global__ void k_degrees(const int* __restrict__ nidx,
                          const int* __restrict__ eidx) {
    int i = blockIdx.x * blockDim.x + threadIdx.x;
    if (i < NNZ) {
        atomicAdd(&g_deg_v[__ldg(&nidx[i])], 1);
        atomicAdd(&g_deg_e[__ldg(&eidx[i])], 1);
    }
}

// ---------------------------------------------------------------------------
// 3-phase exclusive scan of deg -> off/cur (+ inv degree), parallel across SMs.
// Phase A: per-block (TILE-elem) sums
__global__ void k_block_sums(const int* __restrict__ deg, int n,
                             int* __restrict__ bsum) {
    int tid = threadIdx.x;
    int i0 = blockIdx.x * TILE + tid * 4;
    int s = 0;
#pragma unroll
    for (int j = 0; j < 4; j++)
        if (i0 + j < n) s += deg[i0 + j];
    // warp reduce
#pragma unroll
    for (int d = 16; d > 0; d >>= 1) s += __shfl_down_sync(FULL, s, d);
    __shared__ int sh[8];
    int lane = tid & 31, wid = tid >> 5;
    if (lane == 0) sh[wid] = s;
    __syncthreads();
    if (tid == 0) {
        int t = 0;
#pragma unroll
        for (int w = 0; w < 8; w++) t += sh[w];
        bsum[blockIdx.x] = t;
    }
}

// Phase B: single-block exclusive scan of <=128 block sums
__global__ void k_scan_bsums(int* __restrict__ bsum, int nb) {
    __shared__ int sh[128];
    int tid = threadIdx.x;  // 128 threads
    int v = (tid < nb) ? bsum[tid] : 0;
    sh[tid] = v;
    __syncthreads();
    for (int d = 1; d < 128; d <<= 1) {
        int y = (tid >= d) ? sh[tid - d] : 0;
        __syncthreads();
        sh[tid] += y;
        __syncthreads();
    }
    if (tid < nb) bsum[tid] = sh[tid] - v;  // exclusive
}

// Phase C: block-local exclusive scan + apply block base; write off/cur/inv
__global__ void k_scan_apply(const int* __restrict__ deg, int n,
                             const int* __restrict__ bbase,
                             int* __restrict__ off, int* __restrict__ cur,
                             float* __restrict__ inv) {
    int tid = threadIdx.x;          // 256
    int lane = tid & 31, wid = tid >> 5;
    int i0 = blockIdx.x * TILE + tid * 4;
    int v[4];
#pragma unroll
    for (int j = 0; j < 4; j++) v[j] = (i0 + j < n) ? deg[i0 + j] : 0;
    int tsum = v[0] + v[1] + v[2] + v[3];
    // warp inclusive scan of per-thread sums
    int x = tsum;
#pragma unroll
    for (int d = 1; d < 32; d <<= 1) {
        int y = __shfl_up_sync(FULL, x, d);
        if (lane >= d) x += y;
    }
    __shared__ int wsum[8];
    if (lane == 31) wsum[wid] = x;
    __syncthreads();
    if (wid == 0) {
        int w = (lane < 8) ? wsum[lane] : 0;
#pragma unroll
        for (int d = 1; d < 8; d <<= 1) {
            int y = __shfl_up_sync(FULL, w, d);
            if (lane >= d) w += y;
        }
        if (lane < 8) wsum[lane] = w;  // inclusive scan of warp totals
    }
    __syncthreads();
    int wbase = (wid == 0) ? 0 : wsum[wid - 1];
    int run = bbase[blockIdx.x] + wbase + (x - tsum);
#pragma unroll
    for (int j = 0; j < 4; j++) {
        int i = i0 + j;
        if (i < n) {
            off[i] = run;
            cur[i] = run;
            inv[i] = (v[j] > 0) ? (1.0f / (float)v[j]) : 0.0f;
            run += v[j];
        }
    }
    if (blockIdx.x == 0 && tid == 0) off[n] = NNZ;
}

// Build both CSR adjacency lists in one pass.
__global__ void k_permute(const int* __restrict__ nidx,
                          const int* __restrict__ eidx) {
    int i = blockIdx.x * blockDim.x + threadIdx.x;
    if (i >= NNZ) return;
    int nd = __ldg(&nidx[i]);
    int ed = __ldg(&eidx[i]);
    int pe = atomicAdd(&g_cur_e[ed], 1);
    g_csr_e_nodes[pe] = nd;
    int pv = atomicAdd(&g_cur_v[nd], 1);
    g_csr_v_edges[pv] = ed;
}

// ---------------------------------------------------------------------------
// v2e gather: one warp per edge.
// edge_out[e] = sw0 * sum_{n in e}(X[n] * inv_v[n]) + sw1 * Y[e]
__global__ void k_v2e_gather(const float4* __restrict__ X4,
                             const float4* __restrict__ Y4,
                             float4* __restrict__ edge_out4) {
    int e = (blockIdx.x * blockDim.x + threadIdx.x) >> 5;
    int lane = threadIdx.x & 31;
    if (e >= N_EDGES) return;
    int beg = __ldg(&g_off_e[e]);
    int end = __ldg(&g_off_e[e + 1]);
    float4 acc = make_float4(0.f, 0.f, 0.f, 0.f);
    int base = beg;
    // full-batch fast path: 32 indices, compile-time unrolled
    for (; base + 32 <= end; base += 32) {
        int my = __ldg(&g_csr_e_nodes[base + lane]);
#pragma unroll
        for (int t = 0; t < 32; t++) {
            int node = __shfl_sync(FULL, my, t);
            float s = __ldg(&g_inv_v[node]);
            float4 v = __ldg(&X4[(size_t)node * C4 + lane]);
            acc.x += s * v.x; acc.y += s * v.y;
            acc.z += s * v.z; acc.w += s * v.w;
        }
    }
    if (base < end) {
        int cnt = end - base;
        int my = (lane < cnt) ? __ldg(&g_csr_e_nodes[base + lane]) : 0;
        for (int t = 0; t < cnt; t++) {
            int node = __shfl_sync(FULL, my, t);
            float s = __ldg(&g_inv_v[node]);
            float4 v = __ldg(&X4[(size_t)node * C4 + lane]);
            acc.x += s * v.x; acc.y += s * v.y;
            acc.z += s * v.z; acc.w += s * v.w;
        }
    }
    float4 s0 = reinterpret_cast<const float4*>(g_sw0)[lane];
    float4 s1 = reinterpret_cast<const float4*>(g_sw1)[lane];
    float4 y = __ldg(&Y4[(size_t)e * C4 + lane]);
    float4 o;
    o.x = s0.x * acc.x + s1.x * y.x;
    o.y = s0.y * acc.y + s1.y * y.y;
    o.z = s0.z * acc.z + s1.z * y.z;
    o.w = s0.w * acc.w + s1.w * y.w;
    edge_out4[(size_t)e * C4 + lane] = o;
}

// e2v gather: one warp per node.
// node_out[n] = sw0 * sum_{e ni n}(edge_feat[e] * inv_e[e]) + sw1 * X[n]
__global__ void k_e2v_gather(const float4* __restrict__ edge_feat4,
                             const float4* __restrict__ X4,
                             float4* __restrict__ node_out4) {
    int n = (blockIdx.x * blockDim.x + threadIdx.x) >> 5;
    int lane = threadIdx.x & 31;
    if (n >= N_NODES) return;
    int beg = __ldg(&g_off_v[n]);
    int end = __ldg(&g_off_v[n + 1]);
    float4 acc = make_float4(0.f, 0.f, 0.f, 0.f);
    int base = beg;
    for (; base + 32 <= end; base += 32) {
        int my = __ldg(&g_csr_v_edges[base + lane]);
#pragma unroll
        for (int t = 0; t < 32; t++) {
            int edge = __shfl_sync(FULL, my, t);
            float s = __ldg(&g_inv_e[edge]);
            float4 v = __ldg(&edge_feat4[(size_t)edge * C4 + lane]);
            acc.x += s * v.x; acc.y += s * v.y;
            acc.z += s * v.z; acc.w += s * v.w;
        }
    }
    if (base < end) {
        int cnt = end - base;
        int my = (lane < cnt) ? __ldg(&g_csr_v_edges[base + lane]) : 0;
        for (int t = 0; t < cnt; t++) {
            int edge = __shfl_sync(FULL, my, t);
            float s = __ldg(&g_inv_e[edge]);
            float4 v = __ldg(&edge_feat4[(size_t)edge * C4 + lane]);
            acc.x += s * v.x; acc.y += s * v.y;
            acc.z += s * v.z; acc.w += s * v.w;
        }
    }
    float4 s0 = reinterpret_cast<const float4*>(g_sw0)[lane];
    float4 s1 = reinterpret_cast<const float4*>(g_sw1)[lane];
    float4 x = __ldg(&X4[(size_t)n * C4 + lane]);
    float4 o;
    o.x = s0.x * acc.x + s1.x * x.x;
    o.y = s0.y * acc.y + s1.y * x.y;
    o.z = s0.z * acc.z + s1.z * x.z;
    o.w = s0.w * acc.w + s1.w * x.w;
    node_out4[(size_t)n * C4 + lane] = o;
}

// ---------------------------------------------------------------------------
extern "C" void kernel_launch(void* const* d_in, const int* in_sizes, int n_in,
                              void* d_out, int out_size) {
    const float* X    = (const float*)d_in[0];  // [N, C]
    const float* Y    = (const float*)d_in[1];  // [E, C]
    const float* lw   = (const float*)d_in[2];  // [2, C]
    const int*   nidx = (const int*)d_in[3];    // [NNZ]  (JAX demotes int64->int32)
    const int*   eidx = (const int*)d_in[4];    // [NNZ]

    float* node_out = (float*)d_out;                   // [N, C]
    float* edge_out = node_out + (size_t)N_NODES * C;  // [E, C]

    int *p_deg_e, *p_deg_v, *p_off_e, *p_off_v, *p_cur_e, *p_cur_v;
    int *p_bsum_e, *p_bsum_v;
    float *p_inv_e, *p_inv_v;
    cudaGetSymbolAddress((void**)&p_deg_e, g_deg_e);
    cudaGetSymbolAddress((void**)&p_deg_v, g_deg_v);
    cudaGetSymbolAddress((void**)&p_off_e, g_off_e);
    cudaGetSymbolAddress((void**)&p_off_v, g_off_v);
    cudaGetSymbolAddress((void**)&p_cur_e, g_cur_e);
    cudaGetSymbolAddress((void**)&p_cur_v, g_cur_v);
    cudaGetSymbolAddress((void**)&p_bsum_e, g_bsum_e);
    cudaGetSymbolAddress((void**)&p_bsum_v, g_bsum_v);
    cudaGetSymbolAddress((void**)&p_inv_e, g_inv_e);
    cudaGetSymbolAddress((void**)&p_inv_v, g_inv_v);

    const int nb_e = (N_EDGES + TILE - 1) / TILE;  // 49
    const int nb_v = (N_NODES + TILE - 1) / TILE;  // 98

    k_zero_deg<<<(N_NODES + 255) / 256, 256>>>();
    k_softmax<<<1, C>>>(lw);
    k_degrees<<<(NNZ + 255) / 256, 256>>>(nidx, eidx);

    // parallel exclusive scans (edges and nodes)
    k_block_sums<<<nb_e, 256>>>(p_deg_e, N_EDGES, p_bsum_e);
    k_block_sums<<<nb_v, 256>>>(p_deg_v, N_NODES, p_bsum_v);
    k_scan_bsums<<<1, 128>>>(p_bsum_e, nb_e);
    k_scan_bsums<<<1, 128>>>(p_bsum_v, nb_v);
    k_scan_apply<<<nb_e, 256>>>(p_deg_e, N_EDGES, p_bsum_e, p_off_e, p_cur_e, p_inv_e);
    k_scan_apply<<<nb_v, 256>>>(p_deg_v, N_NODES, p_bsum_v, p_off_v, p_cur_v, p_inv_v);

    k_permute<<<(NNZ + 255) / 256, 256>>>(nidx, eidx);

    // Gather passes (warp per row), softmax mix fused in epilogue
    k_v2e_gather<<<(N_EDGES * 32 + 255) / 256, 256>>>(
        (const float4*)X, (const float4*)Y, (float4*)edge_out);
    k_e2v_gather<<<(N_NODES * 32 + 255) / 256, 256>>>(
        (const float4*)edge_out, (const float4*)X, (float4*)node_out);
}

// round 13
// speedup vs baseline: 2.4148x; 1.0271x over previous
#include <cuda_runtime.h>
#include <cstdint>

#define N_NODES 100000
#define N_EDGES 50000
#define C 128
#define C4 (C / 4)
#define NNZ 1600000
#define FULL 0xFFFFFFFFu
#define TILE 1024   // elements per scan block (256 thr x 4)

// ---------------------------------------------------------------------------
// Scratch (allocation-free __device__ globals)
__device__ int   g_deg_v[N_NODES];
__device__ int   g_deg_e[N_EDGES];
__device__ float g_inv_v[N_NODES];
__device__ float g_inv_e[N_EDGES];
__device__ int   g_off_e[N_EDGES + 1];
__device__ int   g_off_v[N_NODES + 1];
__device__ int   g_cur_e[N_EDGES];
__device__ int   g_cur_v[N_NODES];
__device__ int   g_bsum_e[128];
__device__ int   g_bsum_v[128];
__device__ int   g_csr_e_nodes[NNZ];   // per-edge list of incident nodes
__device__ int   g_csr_v_edges[NNZ];   // per-node list of incident edges
__device__ __align__(16) float g_sw0[C];
__device__ __align__(16) float g_sw1[C];

// ---------------------------------------------------------------------------
__global__ void k_zero_deg() {
    int i = blockIdx.x * blockDim.x + threadIdx.x;
    if (i < N_NODES) g_deg_v[i] = 0;
    if (i < N_EDGES) g_deg_e[i] = 0;
}

__global__ void k_softmax(const float* __restrict__ lw) {
    int c = threadIdx.x;  // C threads
    float w0 = lw[c], w1 = lw[C + c];
    float m = fmaxf(w0, w1);
    float e0 = expf(w0 - m), e1 = expf(w1 - m);
    float inv = 1.0f / (e0 + e1);
    g_sw0[c] = e0 * inv;
    g_sw1[c] = e1 * inv;
}

// 4 incidences per thread via int4 loads: 4x atomic ILP per warp.
__global__ void k_degrees(const int4* __restrict__ nidx4,
                          const int4* __restrict__ eidx4) {
    int i = blockIdx.x * blockDim.x + threadIdx.x;
    if (i >= NNZ / 4) return;
    int4 n = __ldg(&nidx4[i]);
    int4 e = __ldg(&eidx4[i]);
    atomicAdd(&g_deg_v[n.x], 1);
    atomicAdd(&g_deg_v[n.y], 1);
    atomicAdd(&g_deg_v[n.z], 1);
    atomicAdd(&g_deg_v[n.w], 1);
    atomicAdd(&g_deg_e[e.x], 1);
    atomicAdd(&g_deg_e[e.y], 1);
    atomicAdd(&g_deg_e[e.z], 1);
    atomicAdd(&g_deg_e[e.w], 1);
}

// ---------------------------------------------------------------------------
// 3-phase exclusive scan of deg -> off/cur (+ inv degree), parallel across SMs.
__global__ void k_block_sums(const int* __restrict__ deg, int n,
                             int* __restrict__ bsum) {
    int tid = threadIdx.x;
    int i0 = blockIdx.x * TILE + tid * 4;
    int s = 0;
#pragma unroll
    for (int j = 0; j < 4; j++)
        if (i0 + j < n) s += deg[i0 + j];
#pragma unroll
    for (int d = 16; d > 0; d >>= 1) s += __shfl_down_sync(FULL, s, d);
    __shared__ int sh[8];
    int lane = tid & 31, wid = tid >> 5;
    if (lane == 0) sh[wid] = s;
    __syncthreads();
    if (tid == 0) {
        int t = 0;
#pragma unroll
        for (int w = 0; w < 8; w++) t += sh[w];
        bsum[blockIdx.x] = t;
    }
}

__global__ void k_scan_bsums(int* __restrict__ bsum, int nb) {
    __shared__ int sh[128];
    int tid = threadIdx.x;  // 128 threads
    int v = (tid < nb) ? bsum[tid] : 0;
    sh[tid] = v;
    __syncthreads();
    for (int d = 1; d < 128; d <<= 1) {
        int y = (tid >= d) ? sh[tid - d] : 0;
        __syncthreads();
        sh[tid] += y;
        __syncthreads();
    }
    if (tid < nb) bsum[tid] = sh[tid] - v;  // exclusive
}

__global__ void k_scan_apply(const int* __restrict__ deg, int n,
                             const int* __restrict__ bbase,
                             int* __restrict__ off, int* __restrict__ cur,
                             float* __restrict__ inv) {
    int tid = threadIdx.x;          // 256
    int lane = tid & 31, wid = tid >> 5;
    int i0 = blockIdx.x * TILE + tid * 4;
    int v[4];
#pragma unroll
    for (int j = 0; j < 4; j++) v[j] = (i0 + j < n) ? deg[i0 + j] : 0;
    int tsum = v[0] + v[1] + v[2] + v[3];
    int x = tsum;
#pragma unroll
    for (int d = 1; d < 32; d <<= 1) {
        int y = __shfl_up_sync(FULL, x, d);
        if (lane >= d) x += y;
    }
    __shared__ int wsum[8];
    if (lane == 31) wsum[wid] = x;
    __syncthreads();
    if (wid == 0) {
        int w = (lane < 8) ? wsum[lane] : 0;
#pragma unroll
        for (int d = 1; d < 8; d <<= 1) {
            int y = __shfl_up_sync(FULL, w, d);
            if (lane >= d) w += y;
        }
        if (lane < 8) wsum[lane] = w;
    }
    __syncthreads();
    int wbase = (wid == 0) ? 0 : wsum[wid - 1];
    int run = bbase[blockIdx.x] + wbase + (x - tsum);
#pragma unroll
    for (int j = 0; j < 4; j++) {
        int i = i0 + j;
        if (i < n) {
            off[i] = run;
            cur[i] = run;
            inv[i] = (v[j] > 0) ? (1.0f / (float)v[j]) : 0.0f;
            run += v[j];
        }
    }
    if (blockIdx.x == 0 && tid == 0) off[n] = NNZ;
}

// Build both CSR adjacency lists; 4 incidences per thread for atomic ILP.
__global__ void k_permute(const int4* __restrict__ nidx4,
                          const int4* __restrict__ eidx4) {
    int i = blockIdx.x * blockDim.x + threadIdx.x;
    if (i >= NNZ / 4) return;
    int4 n = __ldg(&nidx4[i]);
    int4 e = __ldg(&eidx4[i]);
    int nd[4] = {n.x, n.y, n.z, n.w};
    int ed[4] = {e.x, e.y, e.z, e.w};
#pragma unroll
    for (int j = 0; j < 4; j++) {
        int pe = atomicAdd(&g_cur_e[ed[j]], 1);
        g_csr_e_nodes[pe] = nd[j];
        int pv = atomicAdd(&g_cur_v[nd[j]], 1);
        g_csr_v_edges[pv] = ed[j];
    }
}

// ---------------------------------------------------------------------------
// v2e gather: one warp per edge.
// edge_out[e] = sw0 * sum_{n in e}(X[n] * inv_v[n]) + sw1 * Y[e]
__global__ void k_v2e_gather(const float4* __restrict__ X4,
                             const float4* __restrict__ Y4,
                             float4* __restrict__ edge_out4) {
    int e = (blockIdx.x * blockDim.x + threadIdx.x) >> 5;
    int lane = threadIdx.x & 31;
    if (e >= N_EDGES) return;
    int beg = __ldg(&g_off_e[e]);
    int end = __ldg(&g_off_e[e + 1]);
    float4 acc = make_float4(0.f, 0.f, 0.f, 0.f);
    int base = beg;
    // full-batch fast path: indices AND scales preloaded, shfl-broadcast
    for (; base + 32 <= end; base += 32) {
        int   my  = __ldg(&g_csr_e_nodes[base + lane]);
        float smy = __ldg(&g_inv_v[my]);
#pragma unroll
        for (int t = 0; t < 32; t++) {
            int   node = __shfl_sync(FULL, my, t);
            float s    = __shfl_sync(FULL, smy, t);
            float4 v = __ldg(&X4[(size_t)node * C4 + lane]);
            acc.x += s * v.x; acc.y += s * v.y;
            acc.z += s * v.z; acc.w += s * v.w;
        }
    }
    if (base < end) {
        int cnt = end - base;
        int   my  = (lane < cnt) ? __ldg(&g_csr_e_nodes[base + lane]) : 0;
        float smy = (lane < cnt) ? __ldg(&g_inv_v[my]) : 0.f;
        for (int t = 0; t < cnt; t++) {
            int   node = __shfl_sync(FULL, my, t);
            float s    = __shfl_sync(FULL, smy, t);
            float4 v = __ldg(&X4[(size_t)node * C4 + lane]);
            acc.x += s * v.x; acc.y += s * v.y;
            acc.z += s * v.z; acc.w += s * v.w;
        }
    }
    float4 s0 = reinterpret_cast<const float4*>(g_sw0)[lane];
    float4 s1 = reinterpret_cast<const float4*>(g_sw1)[lane];
    float4 y = __ldg(&Y4[(size_t)e * C4 + lane]);
    float4 o;
    o.x = s0.x * acc.x + s1.x * y.x;
    o.y = s0.y * acc.y + s1.y * y.y;
    o.z = s0.z * acc.z + s1.z * y.z;
    o.w = s0.w * acc.w + s1.w * y.w;
    edge_out4[(size_t)e * C4 + lane] = o;
}

// e2v gather: one warp per node.
// node_out[n] = sw0 * sum_{e ni n}(edge_feat[e] * inv_e[e]) + sw1 * X[n]
__global__ void k_e2v_gather(const float4* __restrict__ edge_feat4,
                             const float4* __restrict__ X4,
                             float4* __restrict__ node_out4) {
    int n = (blockIdx.x * blockDim.x + threadIdx.x) >> 5;
    int lane = threadIdx.x & 31;
    if (n >= N_NODES) return;
    int beg = __ldg(&g_off_v[n]);
    int end = __ldg(&g_off_v[n + 1]);
    float4 acc = make_float4(0.f, 0.f, 0.f, 0.f);
    int base = beg;
    for (; base + 32 <= end; base += 32) {
        int   my  = __ldg(&g_csr_v_edges[base + lane]);
        float smy = __ldg(&g_inv_e[my]);
#pragma unroll
        for (int t = 0; t < 32; t++) {
            int   edge = __shfl_sync(FULL, my, t);
            float s    = __shfl_sync(FULL, smy, t);
            float4 v = __ldg(&edge_feat4[(size_t)edge * C4 + lane]);
            acc.x += s * v.x; acc.y += s * v.y;
            acc.z += s * v.z; acc.w += s * v.w;
        }
    }
    if (base < end) {
        int cnt = end - base;
        int   my  = (lane < cnt) ? __ldg(&g_csr_v_edges[base + lane]) : 0;
        float smy = (lane < cnt) ? __ldg(&g_inv_e[my]) : 0.f;
        for (int t = 0; t < cnt; t++) {
            int   edge = __shfl_sync(FULL, my, t);
            float s    = __shfl_sync(FULL, smy, t);
            float4 v = __ldg(&edge_feat4[(size_t)edge * C4 + lane]);
            acc.x += s * v.x; acc.y += s * v.y;
            acc.z += s * v.z; acc.w += s * v.w;
        }
    }
    float4 s0 = reinterpret_cast<const float4*>(g_sw0)[lane];
    float4 s1 = reinterpret_cast<const float4*>(g_sw1)[lane];
    float4 x = __ldg(&X4[(size_t)n * C4 + lane]);
    float4 o;
    o.x = s0.x * acc.x + s1.x * x.x;
    o.y = s0.y * acc.y + s1.y * x.y;
    o.z = s0.z * acc.z + s1.z * x.z;
    o.w = s0.w * acc.w + s1.w * x.w;
    node_out4[(size_t)n * C4 + lane] = o;
}

// ---------------------------------------------------------------------------
extern "C" void kernel_launch(void* const* d_in, const int* in_sizes, int n_in,
                              void* d_out, int out_size) {
    const float* X    = (const float*)d_in[0];  // [N, C]
    const float* Y    = (const float*)d_in[1];  // [E, C]
    const float* lw   = (const float*)d_in[2];  // [2, C]
    const int*   nidx = (const int*)d_in[3];    // [NNZ]  (JAX demotes int64->int32)
    const int*   eidx = (const int*)d_in[4];    // [NNZ]

    float* node_out = (float*)d_out;                   // [N, C]
    float* edge_out = node_out + (size_t)N_NODES * C;  // [E, C]

    int *p_deg_e, *p_deg_v, *p_off_e, *p_off_v, *p_cur_e, *p_cur_v;
    int *p_bsum_e, *p_bsum_v;
    float *p_inv_e, *p_inv_v;
    cudaGetSymbolAddress((void**)&p_deg_e, g_deg_e);
    cudaGetSymbolAddress((void**)&p_deg_v, g_deg_v);
    cudaGetSymbolAddress((void**)&p_off_e, g_off_e);
    cudaGetSymbolAddress((void**)&p_off_v, g_off_v);
    cudaGetSymbolAddress((void**)&p_cur_e, g_cur_e);
    cudaGetSymbolAddress((void**)&p_cur_v, g_cur_v);
    cudaGetSymbolAddress((void**)&p_bsum_e, g_bsum_e);
    cudaGetSymbolAddress((void**)&p_bsum_v, g_bsum_v);
    cudaGetSymbolAddress((void**)&p_inv_e, g_inv_e);
    cudaGetSymbolAddress((void**)&p_inv_v, g_inv_v);

    const int nb_e = (N_EDGES + TILE - 1) / TILE;  // 49
    const int nb_v = (N_NODES + TILE - 1) / TILE;  // 98

    k_zero_deg<<<(N_NODES + 255) / 256, 256>>>();
    k_softmax<<<1, C>>>(lw);
    k_degrees<<<(NNZ / 4 + 255) / 256, 256>>>((const int4*)nidx, (const int4*)eidx);

    // parallel exclusive scans (edges and nodes)
    k_block_sums<<<nb_e, 256>>>(p_deg_e, N_EDGES, p_bsum_e);
    k_block_sums<<<nb_v, 256>>>(p_deg_v, N_NODES, p_bsum_v);
    k_scan_bsums<<<1, 128>>>(p_bsum_e, nb_e);
    k_scan_bsums<<<1, 128>>>(p_bsum_v, nb_v);
    k_scan_apply<<<nb_e, 256>>>(p_deg_e, N_EDGES, p_bsum_e, p_off_e, p_cur_e, p_inv_e);
    k_scan_apply<<<nb_v, 256>>>(p_deg_v, N_NODES, p_bsum_v, p_off_v, p_cur_v, p_inv_v);

    k_permute<<<(NNZ / 4 + 255) / 256, 256>>>((const int4*)nidx, (const int4*)eidx);

    // Gather passes (warp per row), softmax mix fused in epilogue
    k_v2e_gather<<<(N_EDGES * 32 + 255) / 256, 256>>>(
        (const float4*)X, (const float4*)Y, (float4*)edge_out);
    k_e2v_gather<<<(N_NODES * 32 + 255) / 256, 256>>>(
        (const float4*)edge_out, (const float4*)X, (float4*)node_out);
}

// round 14
// speedup vs baseline: 2.6299x; 1.0891x over previous
#include <cuda_runtime.h>
#include <cuda_bf16.h>
#include <cstdint>

#define N_NODES 100000
#define N_EDGES 50000
#define C 128
#define C4 (C / 4)
#define NNZ 1600000
#define FULL 0xFFFFFFFFu
#define TILE 1024   // elements per scan block (256 thr x 4)
#define NB_E ((N_EDGES + TILE - 1) / TILE)   // 49
#define NB_V ((N_NODES + TILE - 1) / TILE)   // 98

// ---------------------------------------------------------------------------
// Scratch (allocation-free __device__ globals)
__device__ int   g_deg_v[N_NODES];
__device__ int   g_deg_e[N_EDGES];
__device__ float g_inv_v[N_NODES];
__device__ float g_inv_e[N_EDGES];
__device__ int   g_off_e[N_EDGES + 1];
__device__ int   g_off_v[N_NODES + 1];
__device__ int   g_cur_e[N_EDGES];
__device__ int   g_cur_v[N_NODES];
__device__ int   g_bsum_e[128];
__device__ int   g_bsum_v[128];
__device__ int   g_csr_e_nodes[NNZ];   // per-edge list of incident nodes
__device__ int   g_csr_v_edges[NNZ];   // per-node list of incident edges
__device__ __align__(16) __nv_bfloat16 g_edge_bf[(size_t)N_EDGES * C];  // edge_feat*inv_e, bf16
__device__ __align__(16) float g_sw0[C];
__device__ __align__(16) float g_sw1[C];

// ---------------------------------------------------------------------------
// init: zero degrees; block 0 also computes softmax weights
__global__ void k_init(const float* __restrict__ lw) {
    int i = blockIdx.x * blockDim.x + threadIdx.x;
    if (i < N_NODES) g_deg_v[i] = 0;
    if (i < N_EDGES) g_deg_e[i] = 0;
    if (blockIdx.x == 0 && threadIdx.x < C) {
        int c = threadIdx.x;
        float w0 = lw[c], w1 = lw[C + c];
        float m = fmaxf(w0, w1);
        float e0 = expf(w0 - m), e1 = expf(w1 - m);
        float inv = 1.0f / (e0 + e1);
        g_sw0[c] = e0 * inv;
        g_sw1[c] = e1 * inv;
    }
}

// 4 incidences per thread via int4 loads: 4x atomic ILP per warp.
__global__ void k_degrees(const int4* __restrict__ nidx4,
                          const int4* __restrict__ eidx4) {
    int i = blockIdx.x * blockDim.x + threadIdx.x;
    if (i >= NNZ / 4) return;
    int4 n = __ldg(&nidx4[i]);
    int4 e = __ldg(&eidx4[i]);
    atomicAdd(&g_deg_v[n.x], 1);
    atomicAdd(&g_deg_v[n.y], 1);
    atomicAdd(&g_deg_v[n.z], 1);
    atomicAdd(&g_deg_v[n.w], 1);
    atomicAdd(&g_deg_e[e.x], 1);
    atomicAdd(&g_deg_e[e.y], 1);
    atomicAdd(&g_deg_e[e.z], 1);
    atomicAdd(&g_deg_e[e.w], 1);
}

// ---------------------------------------------------------------------------
// Phase A (both arrays in one launch): per-block TILE sums
__global__ void k_block_sums_both() {
    bool is_e = blockIdx.x < NB_E;
    const int* deg = is_e ? g_deg_e : g_deg_v;
    int n = is_e ? N_EDGES : N_NODES;
    int* bsum = is_e ? g_bsum_e : g_bsum_v;
    int blk = is_e ? blockIdx.x : blockIdx.x - NB_E;

    int tid = threadIdx.x;
    int i0 = blk * TILE + tid * 4;
    int s = 0;
#pragma unroll
    for (int j = 0; j < 4; j++)
        if (i0 + j < n) s += deg[i0 + j];
#pragma unroll
    for (int d = 16; d > 0; d >>= 1) s += __shfl_down_sync(FULL, s, d);
    __shared__ int sh[8];
    int lane = tid & 31, wid = tid >> 5;
    if (lane == 0) sh[wid] = s;
    __syncthreads();
    if (tid == 0) {
        int t = 0;
#pragma unroll
        for (int w = 0; w < 8; w++) t += sh[w];
        bsum[blk] = t;
    }
}

// Phase B (both arrays, one block): exclusive scan of block sums
__global__ void k_scan_bsums_both() {
    __shared__ int sh[128];
    int tid = threadIdx.x;  // 128 threads
    // edges
    {
        int v = (tid < NB_E) ? g_bsum_e[tid] : 0;
        sh[tid] = v;
        __syncthreads();
        for (int d = 1; d < 128; d <<= 1) {
            int y = (tid >= d) ? sh[tid - d] : 0;
            __syncthreads();
            sh[tid] += y;
            __syncthreads();
        }
        if (tid < NB_E) g_bsum_e[tid] = sh[tid] - v;
        __syncthreads();
    }
    // nodes
    {
        int v = (tid < NB_V) ? g_bsum_v[tid] : 0;
        sh[tid] = v;
        __syncthreads();
        for (int d = 1; d < 128; d <<= 1) {
            int y = (tid >= d) ? sh[tid - d] : 0;
            __syncthreads();
            sh[tid] += y;
            __syncthreads();
        }
        if (tid < NB_V) g_bsum_v[tid] = sh[tid] - v;
    }
}

// Phase C (both arrays in one launch): local scan + apply base; off/cur/inv
__global__ void k_scan_apply_both() {
    bool is_e = blockIdx.x < NB_E;
    const int* deg = is_e ? g_deg_e : g_deg_v;
    int n = is_e ? N_EDGES : N_NODES;
    const int* bbase = is_e ? g_bsum_e : g_bsum_v;
    int* off = is_e ? g_off_e : g_off_v;
    int* cur = is_e ? g_cur_e : g_cur_v;
    float* inv = is_e ? g_inv_e : g_inv_v;
    int blk = is_e ? blockIdx.x : blockIdx.x - NB_E;

    int tid = threadIdx.x;          // 256
    int lane = tid & 31, wid = tid >> 5;
    int i0 = blk * TILE + tid * 4;
    int v[4];
#pragma unroll
    for (int j = 0; j < 4; j++) v[j] = (i0 + j < n) ? deg[i0 + j] : 0;
    int tsum = v[0] + v[1] + v[2] + v[3];
    int x = tsum;
#pragma unroll
    for (int d = 1; d < 32; d <<= 1) {
        int y = __shfl_up_sync(FULL, x, d);
        if (lane >= d) x += y;
    }
    __shared__ int wsum[8];
    if (lane == 31) wsum[wid] = x;
    __syncthreads();
    if (wid == 0) {
        int w = (lane < 8) ? wsum[lane] : 0;
#pragma unroll
        for (int d = 1; d < 8; d <<= 1) {
            int y = __shfl_up_sync(FULL, w, d);
            if (lane >= d) w += y;
        }
        if (lane < 8) wsum[lane] = w;
    }
    __syncthreads();
    int wbase = (wid == 0) ? 0 : wsum[wid - 1];
    int run = bbase[blk] + wbase + (x - tsum);
#pragma unroll
    for (int j = 0; j < 4; j++) {
        int i = i0 + j;
        if (i < n) {
            off[i] = run;
            cur[i] = run;
            inv[i] = (v[j] > 0) ? (1.0f / (float)v[j]) : 0.0f;
            run += v[j];
        }
    }
    if (blk == 0 && tid == 0) off[n] = NNZ;
}

// Build both CSR adjacency lists; 4 incidences per thread for atomic ILP.
__global__ void k_permute(const int4* __restrict__ nidx4,
                          const int4* __restrict__ eidx4) {
    int i = blockIdx.x * blockDim.x + threadIdx.x;
    if (i >= NNZ / 4) return;
    int4 n = __ldg(&nidx4[i]);
    int4 e = __ldg(&eidx4[i]);
    int nd[4] = {n.x, n.y, n.z, n.w};
    int ed[4] = {e.x, e.y, e.z, e.w};
#pragma unroll
    for (int j = 0; j < 4; j++) {
        int pe = atomicAdd(&g_cur_e[ed[j]], 1);
        g_csr_e_nodes[pe] = nd[j];
        int pv = atomicAdd(&g_cur_v[nd[j]], 1);
        g_csr_v_edges[pv] = ed[j];
    }
}

// ---------------------------------------------------------------------------
// v2e gather: one warp per edge.
// edge_out[e] = sw0 * sum_{n in e}(X[n] * inv_v[n]) + sw1 * Y[e]   (fp32, exact)
// Also writes g_edge_bf[e] = bf16(edge_out[e] * inv_e[e]) for the e2v pass.
__global__ void k_v2e_gather(const float4* __restrict__ X4,
                             const float4* __restrict__ Y4,
                             float4* __restrict__ edge_out4) {
    int e = (blockIdx.x * blockDim.x + threadIdx.x) >> 5;
    int lane = threadIdx.x & 31;
    if (e >= N_EDGES) return;
    int beg = __ldg(&g_off_e[e]);
    int end = __ldg(&g_off_e[e + 1]);
    float4 acc = make_float4(0.f, 0.f, 0.f, 0.f);
    int base = beg;
    // full-batch fast path: indices AND scales preloaded, shfl-broadcast
    for (; base + 32 <= end; base += 32) {
        int   my  = __ldg(&g_csr_e_nodes[base + lane]);
        float smy = __ldg(&g_inv_v[my]);
#pragma unroll
        for (int t = 0; t < 32; t++) {
            int   node = __shfl_sync(FULL, my, t);
            float s    = __shfl_sync(FULL, smy, t);
            float4 v = __ldg(&X4[(size_t)node * C4 + lane]);
            acc.x += s * v.x; acc.y += s * v.y;
            acc.z += s * v.z; acc.w += s * v.w;
        }
    }
    if (base < end) {
        int cnt = end - base;
        int   my  = (lane < cnt) ? __ldg(&g_csr_e_nodes[base + lane]) : 0;
        float smy = (lane < cnt) ? __ldg(&g_inv_v[my]) : 0.f;
        for (int t = 0; t < cnt; t++) {
            int   node = __shfl_sync(FULL, my, t);
            float s    = __shfl_sync(FULL, smy, t);
            float4 v = __ldg(&X4[(size_t)node * C4 + lane]);
            acc.x += s * v.x; acc.y += s * v.y;
            acc.z += s * v.z; acc.w += s * v.w;
        }
    }
    float4 s0 = reinterpret_cast<const float4*>(g_sw0)[lane];
    float4 s1 = reinterpret_cast<const float4*>(g_sw1)[lane];
    float4 y = __ldg(&Y4[(size_t)e * C4 + lane]);
    float4 o;
    o.x = s0.x * acc.x + s1.x * y.x;
    o.y = s0.y * acc.y + s1.y * y.y;
    o.z = s0.z * acc.z + s1.z * y.z;
    o.w = s0.w * acc.w + s1.w * y.w;
    edge_out4[(size_t)e * C4 + lane] = o;

    // bf16 scaled copy for e2v (inv_e derived from offsets: deg = end-beg)
    float ie = (end > beg) ? (1.0f / (float)(end - beg)) : 0.0f;
    __nv_bfloat162 p0 = __float22bfloat162_rn(make_float2(o.x * ie, o.y * ie));
    __nv_bfloat162 p1 = __float22bfloat162_rn(make_float2(o.z * ie, o.w * ie));
    uint2 packed;
    packed.x = *reinterpret_cast<unsigned int*>(&p0);
    packed.y = *reinterpret_cast<unsigned int*>(&p1);
    reinterpret_cast<uint2*>(g_edge_bf)[(size_t)e * 32 + lane] = packed;
}

// e2v gather: one warp per node, reading bf16 pre-scaled edge rows (256B/row).
// node_out[n] = sw0 * sum_{e ni n} edge_bf[e] + sw1 * X[n]
__global__ void k_e2v_gather(const float4* __restrict__ X4,
                             float4* __restrict__ node_out4) {
    int n = (blockIdx.x * blockDim.x + threadIdx.x) >> 5;
    int lane = threadIdx.x & 31;
    if (n >= N_NODES) return;
    int beg = __ldg(&g_off_v[n]);
    int end = __ldg(&g_off_v[n + 1]);
    const uint2* EB = reinterpret_cast<const uint2*>(g_edge_bf);
    float4 acc = make_float4(0.f, 0.f, 0.f, 0.f);
    int base = beg;
    for (; base + 32 <= end; base += 32) {
        int my = __ldg(&g_csr_v_edges[base + lane]);
#pragma unroll
        for (int t = 0; t < 32; t++) {
            int edge = __shfl_sync(FULL, my, t);
            uint2 raw = __ldg(&EB[(size_t)edge * 32 + lane]);
            float2 f0 = __bfloat1622float2(*reinterpret_cast<__nv_bfloat162*>(&raw.x));
            float2 f1 = __bfloat1622float2(*reinterpret_cast<__nv_bfloat162*>(&raw.y));
            acc.x += f0.x; acc.y += f0.y;
            acc.z += f1.x; acc.w += f1.y;
        }
    }
    if (base < end) {
        int cnt = end - base;
        int my = (lane < cnt) ? __ldg(&g_csr_v_edges[base + lane]) : 0;
        for (int t = 0; t < cnt; t++) {
            int edge = __shfl_sync(FULL, my, t);
            uint2 raw = __ldg(&EB[(size_t)edge * 32 + lane]);
            float2 f0 = __bfloat1622float2(*reinterpret_cast<__nv_bfloat162*>(&raw.x));
            float2 f1 = __bfloat1622float2(*reinterpret_cast<__nv_bfloat162*>(&raw.y));
            acc.x += f0.x; acc.y += f0.y;
            acc.z += f1.x; acc.w += f1.y;
        }
    }
    float4 s0 = reinterpret_cast<const float4*>(g_sw0)[lane];
    float4 s1 = reinterpret_cast<const float4*>(g_sw1)[lane];
    float4 x = __ldg(&X4[(size_t)n * C4 + lane]);
    float4 o;
    o.x = s0.x * acc.x + s1.x * x.x;
    o.y = s0.y * acc.y + s1.y * x.y;
    o.z = s0.z * acc.z + s1.z * x.z;
    o.w = s0.w * acc.w + s1.w * x.w;
    node_out4[(size_t)n * C4 + lane] = o;
}

// ---------------------------------------------------------------------------
extern "C" void kernel_launch(void* const* d_in, const int* in_sizes, int n_in,
                              void* d_out, int out_size) {
    const float* X    = (const float*)d_in[0];  // [N, C]
    const float* Y    = (const float*)d_in[1];  // [E, C]
    const float* lw   = (const float*)d_in[2];  // [2, C]
    const int*   nidx = (const int*)d_in[3];    // [NNZ]  (JAX demotes int64->int32)
    const int*   eidx = (const int*)d_in[4];    // [NNZ]

    float* node_out = (float*)d_out;                   // [N, C]
    float* edge_out = node_out + (size_t)N_NODES * C;  // [E, C]

    k_init<<<(N_NODES + 255) / 256, 256>>>(lw);
    k_degrees<<<(NNZ / 4 + 255) / 256, 256>>>((const int4*)nidx, (const int4*)eidx);
    k_block_sums_both<<<NB_E + NB_V, 256>>>();
    k_scan_bsums_both<<<1, 128>>>();
    k_scan_apply_both<<<NB_E + NB_V, 256>>>();
    k_permute<<<(NNZ / 4 + 255) / 256, 256>>>((const int4*)nidx, (const int4*)eidx);

    // Gather passes (warp per row), softmax mix fused in epilogue
    k_v2e_gather<<<(N_EDGES * 32 + 255) / 256, 256>>>(
        (const float4*)X, (const float4*)Y, (float4*)edge_out);
    k_e2v_gather<<<(N_NODES * 32 + 255) / 256, 256>>>(
        (const float4*)X, (float4*)node_out);
}

// round 15
// speedup vs baseline: 2.8456x; 1.0820x over previous
#include <cuda_runtime.h>
#include <cuda_bf16.h>
#include <cstdint>

#define N_NODES 100000
#define N_EDGES 50000
#define C 128
#define C4 (C / 4)
#define NNZ 1600000
#define FULL 0xFFFFFFFFu
#define TILE 1024   // elements per scan block (256 thr x 4)
#define NB_E ((N_EDGES + TILE - 1) / TILE)   // 49
#define NB_V ((N_NODES + TILE - 1) / TILE)   // 98
#define NB_ALL (NB_E + NB_V)                 // 147 <= 148 SMs (co-resident)
#define PB ((NNZ / 4 + 255) / 256)           // permute blocks: 1563
#define XB ((N_NODES * C / 8) / 256)         // xnorm blocks: 6250

// ---------------------------------------------------------------------------
// Scratch (allocation-free __device__ globals)
__device__ int   g_deg_v[N_NODES];
__device__ int   g_deg_e[N_EDGES];
__device__ float g_inv_v[N_NODES];
__device__ int   g_off_e[N_EDGES + 1];
__device__ int   g_off_v[N_NODES + 1];
__device__ int   g_cur_e[N_EDGES];
__device__ int   g_cur_v[N_NODES];
__device__ int   g_bsum_all[NB_ALL];
__device__ int   g_scan_ready;
__device__ int   g_csr_e_nodes[NNZ];   // per-edge list of incident nodes
__device__ int   g_csr_v_edges[NNZ];   // per-node list of incident edges
__device__ __align__(16) __nv_bfloat16 g_xnorm_bf[(size_t)N_NODES * C]; // X*inv_v, bf16
__device__ __align__(16) __nv_bfloat16 g_edge_bf[(size_t)N_EDGES * C];  // edge_feat*inv_e, bf16
__device__ __align__(16) float g_sw0[C];
__device__ __align__(16) float g_sw1[C];

// ---------------------------------------------------------------------------
// init: zero degrees + scan counter; block 0 also computes softmax weights
__global__ void k_init(const float* __restrict__ lw) {
    int i = blockIdx.x * blockDim.x + threadIdx.x;
    if (i < N_NODES) g_deg_v[i] = 0;
    if (i < N_EDGES) g_deg_e[i] = 0;
    if (i == 0) g_scan_ready = 0;
    if (blockIdx.x == 0 && threadIdx.x < C) {
        int c = threadIdx.x;
        float w0 = lw[c], w1 = lw[C + c];
        float m = fmaxf(w0, w1);
        float e0 = expf(w0 - m), e1 = expf(w1 - m);
        float inv = 1.0f / (e0 + e1);
        g_sw0[c] = e0 * inv;
        g_sw1[c] = e1 * inv;
    }
}

// 4 incidences per thread via int4 loads: 4x atomic ILP per warp.
__global__ void k_degrees(const int4* __restrict__ nidx4,
                          const int4* __restrict__ eidx4) {
    int i = blockIdx.x * blockDim.x + threadIdx.x;
    if (i >= NNZ / 4) return;
    int4 n = __ldg(&nidx4[i]);
    int4 e = __ldg(&eidx4[i]);
    atomicAdd(&g_deg_v[n.x], 1);
    atomicAdd(&g_deg_v[n.y], 1);
    atomicAdd(&g_deg_v[n.z], 1);
    atomicAdd(&g_deg_v[n.w], 1);
    atomicAdd(&g_deg_e[e.x], 1);
    atomicAdd(&g_deg_e[e.y], 1);
    atomicAdd(&g_deg_e[e.z], 1);
    atomicAdd(&g_deg_e[e.w], 1);
}

// ---------------------------------------------------------------------------
// Fused exclusive scan (single launch): 147 co-resident blocks.
// Each block sums its tile, publishes, spins until all published, then
// computes its prefix base and writes off/cur/inv for its tile.
__global__ void k_scan_fused() {
    int gblk = blockIdx.x;
    bool is_e = gblk < NB_E;
    const int* deg = is_e ? g_deg_e : g_deg_v;
    int n = is_e ? N_EDGES : N_NODES;
    int* off = is_e ? g_off_e : g_off_v;
    int* cur = is_e ? g_cur_e : g_cur_v;
    int blk = is_e ? gblk : gblk - NB_E;
    int dom_start = is_e ? 0 : NB_E;

    int tid = threadIdx.x;          // 256
    int lane = tid & 31, wid = tid >> 5;
    int i0 = blk * TILE + tid * 4;
    int v[4];
#pragma unroll
    for (int j = 0; j < 4; j++) v[j] = (i0 + j < n) ? deg[i0 + j] : 0;
    int tsum = v[0] + v[1] + v[2] + v[3];
    int x = tsum;
#pragma unroll
    for (int d = 1; d < 32; d <<= 1) {
        int y = __shfl_up_sync(FULL, x, d);
        if (lane >= d) x += y;
    }
    __shared__ int wsum[8];
    __shared__ int sh_red[8];
    __shared__ int sh_base;
    if (lane == 31) wsum[wid] = x;
    __syncthreads();
    if (wid == 0) {
        int w = (lane < 8) ? wsum[lane] : 0;
#pragma unroll
        for (int d = 1; d < 8; d <<= 1) {
            int y = __shfl_up_sync(FULL, w, d);
            if (lane >= d) w += y;
        }
        if (lane < 8) wsum[lane] = w;   // inclusive warp-total scan
    }
    __syncthreads();
    int block_total = wsum[7];

    // publish + spin (all 147 blocks resident -> safe)
    if (tid == 0) {
        g_bsum_all[gblk] = block_total;
        __threadfence();
        atomicAdd(&g_scan_ready, 1);
        volatile int* r = &g_scan_ready;
        while (*r < NB_ALL) {}
        __threadfence();
    }
    __syncthreads();

    // prefix base within this domain: sum of bsum_all[dom_start .. dom_start+blk)
    int base = 0;
    for (int j = tid; j < blk; j += 256)
        base += ((volatile int*)g_bsum_all)[dom_start + j];
#pragma unroll
    for (int d = 16; d > 0; d >>= 1) base += __shfl_down_sync(FULL, base, d);
    if (lane == 0) sh_red[wid] = base;
    __syncthreads();
    if (tid == 0) {
        int t = 0;
#pragma unroll
        for (int w = 0; w < 8; w++) t += sh_red[w];
        sh_base = t;
    }
    __syncthreads();

    int wbase = (wid == 0) ? 0 : wsum[wid - 1];
    int run = sh_base + wbase + (x - tsum);
#pragma unroll
    for (int j = 0; j < 4; j++) {
        int i = i0 + j;
        if (i < n) {
            off[i] = run;
            cur[i] = run;
            if (!is_e) g_inv_v[i] = (v[j] > 0) ? (1.0f / (float)v[j]) : 0.0f;
            run += v[j];
        }
    }
    if (blk == 0 && tid == 0) off[n] = NNZ;
}

// ---------------------------------------------------------------------------
// Combined launch: blocks [0,PB) build CSR lists; blocks [PB,PB+XB) compute
// bf16 X_norm = X * inv_v (8 floats -> 8 bf16 per thread).
__global__ void k_permute_xnorm(const int4* __restrict__ nidx4,
                                const int4* __restrict__ eidx4,
                                const float4* __restrict__ X4) {
    if (blockIdx.x < PB) {
        int i = blockIdx.x * blockDim.x + threadIdx.x;
        if (i >= NNZ / 4) return;
        int4 n = __ldg(&nidx4[i]);
        int4 e = __ldg(&eidx4[i]);
        int nd[4] = {n.x, n.y, n.z, n.w};
        int ed[4] = {e.x, e.y, e.z, e.w};
#pragma unroll
        for (int j = 0; j < 4; j++) {
            int pe = atomicAdd(&g_cur_e[ed[j]], 1);
            g_csr_e_nodes[pe] = nd[j];
            int pv = atomicAdd(&g_cur_v[nd[j]], 1);
            g_csr_v_edges[pv] = ed[j];
        }
    } else {
        int t = (blockIdx.x - PB) * blockDim.x + threadIdx.x;  // < N*C/8
        int row = t >> 4;                                       // 16 threads/row
        float s = __ldg(&g_inv_v[row]);
        float4 a = __ldg(&X4[(size_t)t * 2]);
        float4 b = __ldg(&X4[(size_t)t * 2 + 1]);
        __nv_bfloat162 p0 = __float22bfloat162_rn(make_float2(a.x * s, a.y * s));
        __nv_bfloat162 p1 = __float22bfloat162_rn(make_float2(a.z * s, a.w * s));
        __nv_bfloat162 p2 = __float22bfloat162_rn(make_float2(b.x * s, b.y * s));
        __nv_bfloat162 p3 = __float22bfloat162_rn(make_float2(b.z * s, b.w * s));
        uint4 packed;
        packed.x = *reinterpret_cast<unsigned int*>(&p0);
        packed.y = *reinterpret_cast<unsigned int*>(&p1);
        packed.z = *reinterpret_cast<unsigned int*>(&p2);
        packed.w = *reinterpret_cast<unsigned int*>(&p3);
        reinterpret_cast<uint4*>(g_xnorm_bf)[t] = packed;
    }
}

// ---------------------------------------------------------------------------
// v2e gather: one warp per edge, reading bf16 pre-scaled node rows (256B/row).
// edge_out[e] = sw0 * sum_{n in e} xnorm_bf[n] + sw1 * Y[e]   (fp32 out)
// Also writes g_edge_bf[e] = bf16(edge_out[e] * inv_e[e]) for the e2v pass.
__global__ void k_v2e_gather(const float4* __restrict__ Y4,
                             float4* __restrict__ edge_out4) {
    int e = (blockIdx.x * blockDim.x + threadIdx.x) >> 5;
    int lane = threadIdx.x & 31;
    if (e >= N_EDGES) return;
    int beg = __ldg(&g_off_e[e]);
    int end = __ldg(&g_off_e[e + 1]);
    const uint2* XB2 = reinterpret_cast<const uint2*>(g_xnorm_bf);
    float4 acc = make_float4(0.f, 0.f, 0.f, 0.f);
    int base = beg;
    for (; base + 32 <= end; base += 32) {
        int my = __ldg(&g_csr_e_nodes[base + lane]);
#pragma unroll
        for (int t = 0; t < 32; t++) {
            int node = __shfl_sync(FULL, my, t);
            uint2 raw = __ldg(&XB2[(size_t)node * 32 + lane]);
            float2 f0 = __bfloat1622float2(*reinterpret_cast<__nv_bfloat162*>(&raw.x));
            float2 f1 = __bfloat1622float2(*reinterpret_cast<__nv_bfloat162*>(&raw.y));
            acc.x += f0.x; acc.y += f0.y;
            acc.z += f1.x; acc.w += f1.y;
        }
    }
    if (base < end) {
        int cnt = end - base;
        int my = (lane < cnt) ? __ldg(&g_csr_e_nodes[base + lane]) : 0;
        for (int t = 0; t < cnt; t++) {
            int node = __shfl_sync(FULL, my, t);
            uint2 raw = __ldg(&XB2[(size_t)node * 32 + lane]);
            float2 f0 = __bfloat1622float2(*reinterpret_cast<__nv_bfloat162*>(&raw.x));
            float2 f1 = __bfloat1622float2(*reinterpret_cast<__nv_bfloat162*>(&raw.y));
            acc.x += f0.x; acc.y += f0.y;
            acc.z += f1.x; acc.w += f1.y;
        }
    }
    float4 s0 = reinterpret_cast<const float4*>(g_sw0)[lane];
    float4 s1 = reinterpret_cast<const float4*>(g_sw1)[lane];
    float4 y = __ldg(&Y4[(size_t)e * C4 + lane]);
    float4 o;
    o.x = s0.x * acc.x + s1.x * y.x;
    o.y = s0.y * acc.y + s1.y * y.y;
    o.z = s0.z * acc.z + s1.z * y.z;
    o.w = s0.w * acc.w + s1.w * y.w;
    edge_out4[(size_t)e * C4 + lane] = o;

    // bf16 scaled copy for e2v (inv_e derived from offsets: deg = end-beg)
    float ie = (end > beg) ? (1.0f / (float)(end - beg)) : 0.0f;
    __nv_bfloat162 p0 = __float22bfloat162_rn(make_float2(o.x * ie, o.y * ie));
    __nv_bfloat162 p1 = __float22bfloat162_rn(make_float2(o.z * ie, o.w * ie));
    uint2 packed;
    packed.x = *reinterpret_cast<unsigned int*>(&p0);
    packed.y = *reinterpret_cast<unsigned int*>(&p1);
    reinterpret_cast<uint2*>(g_edge_bf)[(size_t)e * 32 + lane] = packed;
}

// e2v gather: one warp per node, reading bf16 pre-scaled edge rows (256B/row).
// node_out[n] = sw0 * sum_{e ni n} edge_bf[e] + sw1 * X[n]
__global__ void k_e2v_gather(const float4* __restrict__ X4,
                             float4* __restrict__ node_out4) {
    int n = (blockIdx.x * blockDim.x + threadIdx.x) >> 5;
    int lane = threadIdx.x & 31;
    if (n >= N_NODES) return;
    int beg = __ldg(&g_off_v[n]);
    int end = __ldg(&g_off_v[n + 1]);
    const uint2* EB = reinterpret_cast<const uint2*>(g_edge_bf);
    float4 acc = make_float4(0.f, 0.f, 0.f, 0.f);
    int base = beg;
    for (; base + 32 <= end; base += 32) {
        int my = __ldg(&g_csr_v_edges[base + lane]);
#pragma unroll
        for (int t = 0; t < 32; t++) {
            int edge = __shfl_sync(FULL, my, t);
            uint2 raw = __ldg(&EB[(size_t)edge * 32 + lane]);
            float2 f0 = __bfloat1622float2(*reinterpret_cast<__nv_bfloat162*>(&raw.x));
            float2 f1 = __bfloat1622float2(*reinterpret_cast<__nv_bfloat162*>(&raw.y));
            acc.x += f0.x; acc.y += f0.y;
            acc.z += f1.x; acc.w += f1.y;
        }
    }
    if (base < end) {
        int cnt = end - base;
        int my = (lane < cnt) ? __ldg(&g_csr_v_edges[base + lane]) : 0;
        for (int t = 0; t < cnt; t++) {
            int edge = __shfl_sync(FULL, my, t);
            uint2 raw = __ldg(&EB[(size_t)edge * 32 + lane]);
            float2 f0 = __bfloat1622float2(*reinterpret_cast<__nv_bfloat162*>(&raw.x));
            float2 f1 = __bfloat1622float2(*reinterpret_cast<__nv_bfloat162*>(&raw.y));
            acc.x += f0.x; acc.y += f0.y;
            acc.z += f1.x; acc.w += f1.y;
        }
    }
    float4 s0 = reinterpret_cast<const float4*>(g_sw0)[lane];
    float4 s1 = reinterpret_cast<const float4*>(g_sw1)[lane];
    float4 x = __ldg(&X4[(size_t)n * C4 + lane]);
    float4 o;
    o.x = s0.x * acc.x + s1.x * x.x;
    o.y = s0.y * acc.y + s1.y * x.y;
    o.z = s0.z * acc.z + s1.z * x.z;
    o.w = s0.w * acc.w + s1.w * x.w;
    node_out4[(size_t)n * C4 + lane] = o;
}

// ---------------------------------------------------------------------------
extern "C" void kernel_launch(void* const* d_in, const int* in_sizes, int n_in,
                              void* d_out, int out_size) {
    const float* X    = (const float*)d_in[0];  // [N, C]
    const float* Y    = (const float*)d_in[1];  // [E, C]
    const float* lw   = (const float*)d_in[2];  // [2, C]
    const int*   nidx = (const int*)d_in[3];    // [NNZ]  (JAX demotes int64->int32)
    const int*   eidx = (const int*)d_in[4];    // [NNZ]

    float* node_out = (float*)d_out;                   // [N, C]
    float* edge_out = node_out + (size_t)N_NODES * C;  // [E, C]

    k_init<<<(N_NODES + 255) / 256, 256>>>(lw);
    k_degrees<<<(NNZ / 4 + 255) / 256, 256>>>((const int4*)nidx, (const int4*)eidx);
    k_scan_fused<<<NB_ALL, 256>>>();
    k_permute_xnorm<<<PB + XB, 256>>>((const int4*)nidx, (const int4*)eidx,
                                      (const float4*)X);
    k_v2e_gather<<<(N_EDGES * 32 + 255) / 256, 256>>>(
        (const float4*)Y, (float4*)edge_out);
    k_e2v_gather<<<(N_NODES * 32 + 255) / 256, 256>>>(
        (const float4*)X, (float4*)node_out);
}

// round 16
// speedup vs baseline: 3.0064x; 1.0565x over previous
#include <cuda_runtime.h>
#include <cuda_fp16.h>
#include <cstdint>

#define N_NODES 100000
#define N_EDGES 50000
#define C 128
#define C4 (C / 4)
#define NNZ 1600000
#define FULL 0xFFFFFFFFu
#define TILE 1024   // elements per scan block (256 thr x 4)
#define NB_E ((N_EDGES + TILE - 1) / TILE)   // 49
#define NB_V ((N_NODES + TILE - 1) / TILE)   // 98
#define NB_ALL (NB_E + NB_V)                 // 147 <= 148 SMs (co-resident)
#define PB ((NNZ / 4 + 255) / 256)           // permute blocks: 1563
#define XB ((N_NODES * C / 8) / 256)         // xnorm blocks: 6250

// ---------------------------------------------------------------------------
// Scratch (allocation-free __device__ globals; zero-initialized at load).
// Invariant maintained across calls: g_deg_* are ZERO at kernel_launch entry
// (k_scan_fused re-zeroes them after reading).
__device__ int   g_deg_v[N_NODES];
__device__ int   g_deg_e[N_EDGES];
__device__ float g_inv_v[N_NODES];
__device__ int   g_off_e[N_EDGES + 1];
__device__ int   g_off_v[N_NODES + 1];
__device__ int   g_cur_e[N_EDGES];
__device__ int   g_cur_v[N_NODES];
__device__ int   g_bsum_all[NB_ALL];
__device__ int   g_scan_ready;
__device__ int   g_csr_e_nodes[NNZ];   // per-edge list of incident nodes
__device__ int   g_csr_v_edges[NNZ];   // per-node list of incident edges
__device__ __align__(16) __half g_xnorm_h[(size_t)N_NODES * C]; // X*inv_v, fp16
__device__ __align__(16) __half g_edge_h[(size_t)N_EDGES * C];  // edge_feat*inv_e, fp16
__device__ __align__(16) float g_sw0[C];
__device__ __align__(16) float g_sw1[C];

// ---------------------------------------------------------------------------
// init (1 block): softmax weights + scan counter reset
__global__ void k_init(const float* __restrict__ lw) {
    if (threadIdx.x == 0) g_scan_ready = 0;
    if (threadIdx.x < C) {
        int c = threadIdx.x;
        float w0 = lw[c], w1 = lw[C + c];
        float m = fmaxf(w0, w1);
        float e0 = expf(w0 - m), e1 = expf(w1 - m);
        float inv = 1.0f / (e0 + e1);
        g_sw0[c] = e0 * inv;
        g_sw1[c] = e1 * inv;
    }
}

// 4 incidences per thread via int4 loads: 4x atomic ILP per warp.
__global__ void k_degrees(const int4* __restrict__ nidx4,
                          const int4* __restrict__ eidx4) {
    int i = blockIdx.x * blockDim.x + threadIdx.x;
    if (i >= NNZ / 4) return;
    int4 n = __ldg(&nidx4[i]);
    int4 e = __ldg(&eidx4[i]);
    atomicAdd(&g_deg_v[n.x], 1);
    atomicAdd(&g_deg_v[n.y], 1);
    atomicAdd(&g_deg_v[n.z], 1);
    atomicAdd(&g_deg_v[n.w], 1);
    atomicAdd(&g_deg_e[e.x], 1);
    atomicAdd(&g_deg_e[e.y], 1);
    atomicAdd(&g_deg_e[e.z], 1);
    atomicAdd(&g_deg_e[e.w], 1);
}

// ---------------------------------------------------------------------------
// Fused exclusive scan (single launch): 147 co-resident blocks.
// Also re-zeroes the deg arrays after reading (invariant for next call).
__global__ void k_scan_fused() {
    int gblk = blockIdx.x;
    bool is_e = gblk < NB_E;
    int* degp = is_e ? g_deg_e : g_deg_v;
    int n = is_e ? N_EDGES : N_NODES;
    int* off = is_e ? g_off_e : g_off_v;
    int* cur = is_e ? g_cur_e : g_cur_v;
    int blk = is_e ? gblk : gblk - NB_E;
    int dom_start = is_e ? 0 : NB_E;

    int tid = threadIdx.x;          // 256
    int lane = tid & 31, wid = tid >> 5;
    int i0 = blk * TILE + tid * 4;
    int v[4];
#pragma unroll
    for (int j = 0; j < 4; j++) v[j] = (i0 + j < n) ? degp[i0 + j] : 0;
    // re-zero for next call (same lines, already hot)
#pragma unroll
    for (int j = 0; j < 4; j++) if (i0 + j < n) degp[i0 + j] = 0;

    int tsum = v[0] + v[1] + v[2] + v[3];
    int x = tsum;
#pragma unroll
    for (int d = 1; d < 32; d <<= 1) {
        int y = __shfl_up_sync(FULL, x, d);
        if (lane >= d) x += y;
    }
    __shared__ int wsum[8];
    __shared__ int sh_red[8];
    __shared__ int sh_base;
    if (lane == 31) wsum[wid] = x;
    __syncthreads();
    if (wid == 0) {
        int w = (lane < 8) ? wsum[lane] : 0;
#pragma unroll
        for (int d = 1; d < 8; d <<= 1) {
            int y = __shfl_up_sync(FULL, w, d);
            if (lane >= d) w += y;
        }
        if (lane < 8) wsum[lane] = w;   // inclusive warp-total scan
    }
    __syncthreads();
    int block_total = wsum[7];

    // publish + spin (all 147 blocks resident -> safe)
    if (tid == 0) {
        g_bsum_all[gblk] = block_total;
        __threadfence();
        atomicAdd(&g_scan_ready, 1);
        volatile int* r = &g_scan_ready;
        while (*r < NB_ALL) {}
        __threadfence();
    }
    __syncthreads();

    // prefix base within this domain
    int base = 0;
    for (int j = tid; j < blk; j += 256)
        base += ((volatile int*)g_bsum_all)[dom_start + j];
#pragma unroll
    for (int d = 16; d > 0; d >>= 1) base += __shfl_down_sync(FULL, base, d);
    if (lane == 0) sh_red[wid] = base;
    __syncthreads();
    if (tid == 0) {
        int t = 0;
#pragma unroll
        for (int w = 0; w < 8; w++) t += sh_red[w];
        sh_base = t;
    }
    __syncthreads();

    int wbase = (wid == 0) ? 0 : wsum[wid - 1];
    int run = sh_base + wbase + (x - tsum);
#pragma unroll
    for (int j = 0; j < 4; j++) {
        int i = i0 + j;
        if (i < n) {
            off[i] = run;
            cur[i] = run;
            if (!is_e) g_inv_v[i] = (v[j] > 0) ? (1.0f / (float)v[j]) : 0.0f;
            run += v[j];
        }
    }
    if (blk == 0 && tid == 0) off[n] = NNZ;
}

// ---------------------------------------------------------------------------
// Combined launch: blocks [0,PB) build CSR lists (all 8 atomics batched before
// dependent stores for max MLP); blocks [PB,PB+XB) compute fp16 X_norm.
__global__ void k_permute_xnorm(const int4* __restrict__ nidx4,
                                const int4* __restrict__ eidx4,
                                const float4* __restrict__ X4) {
    if (blockIdx.x < PB) {
        int i = blockIdx.x * blockDim.x + threadIdx.x;
        if (i >= NNZ / 4) return;
        int4 n = __ldg(&nidx4[i]);
        int4 e = __ldg(&eidx4[i]);
        int nd[4] = {n.x, n.y, n.z, n.w};
        int ed[4] = {e.x, e.y, e.z, e.w};
        int pe[4], pv[4];
#pragma unroll
        for (int j = 0; j < 4; j++) pe[j] = atomicAdd(&g_cur_e[ed[j]], 1);
#pragma unroll
        for (int j = 0; j < 4; j++) pv[j] = atomicAdd(&g_cur_v[nd[j]], 1);
#pragma unroll
        for (int j = 0; j < 4; j++) g_csr_e_nodes[pe[j]] = nd[j];
#pragma unroll
        for (int j = 0; j < 4; j++) g_csr_v_edges[pv[j]] = ed[j];
    } else {
        int t = (blockIdx.x - PB) * blockDim.x + threadIdx.x;  // < N*C/8
        int row = t >> 4;                                       // 16 threads/row
        float s = __ldg(&g_inv_v[row]);
        float4 a = __ldg(&X4[(size_t)t * 2]);
        float4 b = __ldg(&X4[(size_t)t * 2 + 1]);
        __half2 p0 = __float22half2_rn(make_float2(a.x * s, a.y * s));
        __half2 p1 = __float22half2_rn(make_float2(a.z * s, a.w * s));
        __half2 p2 = __float22half2_rn(make_float2(b.x * s, b.y * s));
        __half2 p3 = __float22half2_rn(make_float2(b.z * s, b.w * s));
        uint4 packed;
        packed.x = *reinterpret_cast<unsigned int*>(&p0);
        packed.y = *reinterpret_cast<unsigned int*>(&p1);
        packed.z = *reinterpret_cast<unsigned int*>(&p2);
        packed.w = *reinterpret_cast<unsigned int*>(&p3);
        reinterpret_cast<uint4*>(g_xnorm_h)[t] = packed;
    }
}

// ---------------------------------------------------------------------------
// v2e gather: one warp per edge, reading fp16 pre-scaled node rows (256B/row).
// edge_out[e] = sw0 * sum_{n in e} xnorm_h[n] + sw1 * Y[e]   (fp32 out)
// Also writes g_edge_h[e] = fp16(edge_out[e] * inv_e[e]) for the e2v pass.
__global__ void k_v2e_gather(const float4* __restrict__ Y4,
                             float4* __restrict__ edge_out4) {
    int e = (blockIdx.x * blockDim.x + threadIdx.x) >> 5;
    int lane = threadIdx.x & 31;
    if (e >= N_EDGES) return;
    int beg = __ldg(&g_off_e[e]);
    int end = __ldg(&g_off_e[e + 1]);
    const uint2* XH = reinterpret_cast<const uint2*>(g_xnorm_h);
    float4 acc = make_float4(0.f, 0.f, 0.f, 0.f);
    int base = beg;
    for (; base + 32 <= end; base += 32) {
        int my = __ldg(&g_csr_e_nodes[base + lane]);
#pragma unroll
        for (int t = 0; t < 32; t++) {
            int node = __shfl_sync(FULL, my, t);
            uint2 raw = __ldg(&XH[(size_t)node * 32 + lane]);
            float2 f0 = __half22float2(*reinterpret_cast<__half2*>(&raw.x));
            float2 f1 = __half22float2(*reinterpret_cast<__half2*>(&raw.y));
            acc.x += f0.x; acc.y += f0.y;
            acc.z += f1.x; acc.w += f1.y;
        }
    }
    if (base < end) {
        int cnt = end - base;
        int my = (lane < cnt) ? __ldg(&g_csr_e_nodes[base + lane]) : 0;
        for (int t = 0; t < cnt; t++) {
            int node = __shfl_sync(FULL, my, t);
            uint2 raw = __ldg(&XH[(size_t)node * 32 + lane]);
            float2 f0 = __half22float2(*reinterpret_cast<__half2*>(&raw.x));
            float2 f1 = __half22float2(*reinterpret_cast<__half2*>(&raw.y));
            acc.x += f0.x; acc.y += f0.y;
            acc.z += f1.x; acc.w += f1.y;
        }
    }
    float4 s0 = reinterpret_cast<const float4*>(g_sw0)[lane];
    float4 s1 = reinterpret_cast<const float4*>(g_sw1)[lane];
    float4 y = __ldg(&Y4[(size_t)e * C4 + lane]);
    float4 o;
    o.x = s0.x * acc.x + s1.x * y.x;
    o.y = s0.y * acc.y + s1.y * y.y;
    o.z = s0.z * acc.z + s1.z * y.z;
    o.w = s0.w * acc.w + s1.w * y.w;
    edge_out4[(size_t)e * C4 + lane] = o;

    // fp16 scaled copy for e2v (inv_e derived from offsets: deg = end-beg)
    float ie = (end > beg) ? (1.0f / (float)(end - beg)) : 0.0f;
    __half2 p0 = __float22half2_rn(make_float2(o.x * ie, o.y * ie));
    __half2 p1 = __float22half2_rn(make_float2(o.z * ie, o.w * ie));
    uint2 packed;
    packed.x = *reinterpret_cast<unsigned int*>(&p0);
    packed.y = *reinterpret_cast<unsigned int*>(&p1);
    reinterpret_cast<uint2*>(g_edge_h)[(size_t)e * 32 + lane] = packed;
}

// e2v gather: one warp per node, reading fp16 pre-scaled edge rows (256B/row).
// node_out[n] = sw0 * sum_{e ni n} edge_h[e] + sw1 * X[n]
__global__ void k_e2v_gather(const float4* __restrict__ X4,
                             float4* __restrict__ node_out4) {
    int n = (blockIdx.x * blockDim.x + threadIdx.x) >> 5;
    int lane = threadIdx.x & 31;
    if (n >= N_NODES) return;
    int beg = __ldg(&g_off_v[n]);
    int end = __ldg(&g_off_v[n + 1]);
    const uint2* EH = reinterpret_cast<const uint2*>(g_edge_h);
    float4 acc = make_float4(0.f, 0.f, 0.f, 0.f);
    int base = beg;
    for (; base + 32 <= end; base += 32) {
        int my = __ldg(&g_csr_v_edges[base + lane]);
#pragma unroll
        for (int t = 0; t < 32; t++) {
            int edge = __shfl_sync(FULL, my, t);
            uint2 raw = __ldg(&EH[(size_t)edge * 32 + lane]);
            float2 f0 = __half22float2(*reinterpret_cast<__half2*>(&raw.x));
            float2 f1 = __half22float2(*reinterpret_cast<__half2*>(&raw.y));
            acc.x += f0.x; acc.y += f0.y;
            acc.z += f1.x; acc.w += f1.y;
        }
    }
    if (base < end) {
        int cnt = end - base;
        int my = (lane < cnt) ? __ldg(&g_csr_v_edges[base + lane]) : 0;
        for (int t = 0; t < cnt; t++) {
            int edge = __shfl_sync(FULL, my, t);
            uint2 raw = __ldg(&EH[(size_t)edge * 32 + lane]);
            float2 f0 = __half22float2(*reinterpret_cast<__half2*>(&raw.x));
            float2 f1 = __half22float2(*reinterpret_cast<__half2*>(&raw.y));
            acc.x += f0.x; acc.y += f0.y;
            acc.z += f1.x; acc.w += f1.y;
        }
    }
    float4 s0 = reinterpret_cast<const float4*>(g_sw0)[lane];
    float4 s1 = reinterpret_cast<const float4*>(g_sw1)[lane];
    float4 x = __ldg(&X4[(size_t)n * C4 + lane]);
    float4 o;
    o.x = s0.x * acc.x + s1.x * x.x;
    o.y = s0.y * acc.y + s1.y * x.y;
    o.z = s0.z * acc.z + s1.z * x.z;
    o.w = s0.w * acc.w + s1.w * x.w;
    node_out4[(size_t)n * C4 + lane] = o;
}

// ---------------------------------------------------------------------------
extern "C" void kernel_launch(void* const* d_in, const int* in_sizes, int n_in,
                              void* d_out, int out_size) {
    const float* X    = (const float*)d_in[0];  // [N, C]
    const float* Y    = (const float*)d_in[1];  // [E, C]
    const float* lw   = (const float*)d_in[2];  // [2, C]
    const int*   nidx = (const int*)d_in[3];    // [NNZ]  (JAX demotes int64->int32)
    const int*   eidx = (const int*)d_in[4];    // [NNZ]

    float* node_out = (float*)d_out;                   // [N, C]
    float* edge_out = node_out + (size_t)N_NODES * C;  // [E, C]

    k_init<<<1, 128>>>(lw);
    k_degrees<<<(NNZ / 4 + 255) / 256, 256>>>((const int4*)nidx, (const int4*)eidx);
    k_scan_fused<<<NB_ALL, 256>>>();
    k_permute_xnorm<<<PB + XB, 256>>>((const int4*)nidx, (const int4*)eidx,
                                      (const float4*)X);
    k_v2e_gather<<<(N_EDGES * 32 + 255) / 256, 256>>>(
        (const float4*)Y, (float4*)edge_out);
    k_e2v_gather<<<(N_NODES * 32 + 255) / 256, 256>>>(
        (const float4*)X, (float4*)node_out);
}